// round 12
// baseline (speedup 1.0000x reference)
#include <cuda_runtime.h>

// Problem constants (fixed by the dataset: pcd [8, 4096, 3] fp32, k = 5)
#define NB 8
#define NPTS 4096
#define KNN 5
#define NSPLIT 4
#define MSEG (NPTS / NSPLIT)       // 1024 points per segment
#define MPAIR (MSEG / 2)           // 512 point-pairs
#define TPB 128
#define QPT 2                      // queries per thread
#define QPC (TPB * QPT)            // 256 queries per CTA
#define CHUNKS (NPTS / QPC)        // 16 query chunks per batch

typedef unsigned long long u64;

// Scratch (allocation-free rule -> __device__ globals)
__device__ float g_key[NSPLIT][NB * NPTS * KNN];
__device__ int   g_idx[NSPLIT][NB * NPTS * KNN];
__device__ float g_partial[NB * 16];   // per-merge-CTA trace partial sums

// Packed f32x2 helpers (Blackwell FFMA2 is PTX-only).
__device__ __forceinline__ u64 pack2(float lo, float hi) {
    u64 r;
    asm("mov.b64 %0, {%1, %2};" : "=l"(r)
        : "r"(__float_as_uint(lo)), "r"(__float_as_uint(hi)));
    return r;
}
__device__ __forceinline__ u64 ffma2(u64 a, u64 b, u64 c) {
    u64 d;
    asm("fma.rn.f32x2 %0, %1, %2, %3;" : "=l"(d) : "l"(a), "l"(b), "l"(c));
    return d;
}
__device__ __forceinline__ void unpack2(u64 v, float& lo, float& hi) {
    unsigned l, h;
    asm("mov.b64 {%0, %1}, %2;" : "=r"(l), "=r"(h) : "l"(v));
    lo = __uint_as_float(l);
    hi = __uint_as_float(h);
}

// --------------------------------------------------------------------------
// Kernel A: per-(query, point-segment) top-5 scan, pair-packed, TWO queries
// per thread under a merged rare-branch.
// CTA = 256 queries x one quarter of the points. Segment staged as 512
// pairs: shA[m] = (x0x1, y0y1), shB[m] = (z0z1, |p0|^2|p1|^2), 16KB.
// Per pair: 2 x LDS.128 + 6 x FFMA2 -> two keys per query; the insert branch
// covers both queries (one warp-coherent event instead of two).
// key_j = |p_j|^2 - 2 q.p_j (monotone in d^2 for fixed q; strict '<'
// displacement keeps the lowest index on ties, matching jax.lax.top_k).
// --------------------------------------------------------------------------
__global__ __launch_bounds__(TPB) void knn_scan_kernel(const float* __restrict__ pcd)
{
    __shared__ ulonglong2 shA[MPAIR];   // 8 KB: x-pair, y-pair
    __shared__ ulonglong2 shB[MPAIR];   // 8 KB: z-pair, w-pair

    const int seg   = blockIdx.x & (NSPLIT - 1);
    const int chunk = (blockIdx.x >> 2) % CHUNKS;
    const int b     = blockIdx.x / (NSPLIT * CHUNKS);

    const float* base = pcd + (size_t)b * NPTS * 3;
    const int p0 = seg * MSEG;

    for (int m = threadIdx.x; m < MPAIR; m += TPB) {
        const float* pp = base + (size_t)(p0 + 2 * m) * 3;
        float x0 = pp[0], y0 = pp[1], z0 = pp[2];
        float x1 = pp[3], y1 = pp[4], z1 = pp[5];
        float w0 = fmaf(x0, x0, fmaf(y0, y0, z0 * z0));
        float w1 = fmaf(x1, x1, fmaf(y1, y1, z1 * z1));
        ulonglong2 va, vb;
        va.x = pack2(x0, x1);  va.y = pack2(y0, y1);
        vb.x = pack2(z0, z1);  vb.y = pack2(w0, w1);
        shA[m] = va;
        shB[m] = vb;
    }
    __syncthreads();

    const int qiA = chunk * QPC + threadIdx.x;          // query A
    const int qiB = qiA + TPB;                          // query B
    const float qAx = base[qiA * 3 + 0], qAy = base[qiA * 3 + 1], qAz = base[qiA * 3 + 2];
    const float qBx = base[qiB * 3 + 0], qBy = base[qiB * 3 + 1], qBz = base[qiB * 3 + 2];
    const u64 nxA = pack2(-2.0f * qAx, -2.0f * qAx);
    const u64 nyA = pack2(-2.0f * qAy, -2.0f * qAy);
    const u64 nzA = pack2(-2.0f * qAz, -2.0f * qAz);
    const u64 nxB = pack2(-2.0f * qBx, -2.0f * qBx);
    const u64 nyB = pack2(-2.0f * qBy, -2.0f * qBy);
    const u64 nzB = pack2(-2.0f * qBz, -2.0f * qBz);

    // Exact sorted top-5 per query (ascending); named scalars -> registers.
    float ak0 = 3.4e38f, ak1 = 3.4e38f, ak2 = 3.4e38f, ak3 = 3.4e38f, ak4 = 3.4e38f;
    int   ai0 = 0, ai1 = 0, ai2 = 0, ai3 = 0, ai4 = 0;
    float ck0 = 3.4e38f, ck1 = 3.4e38f, ck2 = 3.4e38f, ck3 = 3.4e38f, ck4 = 3.4e38f;
    int   ci0 = 0, ci1 = 0, ci2 = 0, ci3 = 0, ci4 = 0;

#define INS(K0, K1, K2, K3, K4, I0, I1, I2, I3, I4, KEY, JIDX)                \
    if ((KEY) < K4) {                                                         \
        float key = (KEY);                                                    \
        bool lt0 = key < K0;                                                  \
        bool lt1 = key < K1;                                                  \
        bool lt2 = key < K2;                                                  \
        bool lt3 = key < K3;                                                  \
        K4 = lt3 ? K3 : key;  I4 = lt3 ? I3 : (JIDX);                         \
        if (lt3) { K3 = lt2 ? K2 : key;  I3 = lt2 ? I2 : (JIDX); }            \
        if (lt2) { K2 = lt1 ? K1 : key;  I2 = lt1 ? I1 : (JIDX); }            \
        if (lt1) { K1 = lt0 ? K0 : key;  I1 = lt0 ? I0 : (JIDX); }            \
        if (lt0) { K0 = key;             I0 = (JIDX); }                       \
    }

// Process one pair for both queries under ONE merged rare-branch.
#define PAIR(VA, VB, JB)                                                      \
    {                                                                         \
        u64 kka = ffma2((VA).x, nxA, ffma2((VA).y, nyA, ffma2((VB).x, nzA, (VB).y))); \
        u64 kkb = ffma2((VA).x, nxB, ffma2((VA).y, nyB, ffma2((VB).x, nzB, (VB).y))); \
        float a0, a1, b0, b1;                                                 \
        unpack2(kka, a0, a1);                                                 \
        unpack2(kkb, b0, b1);                                                 \
        float mna = fminf(a0, a1), mnb = fminf(b0, b1);                       \
        if (mna < ak4 || mnb < ck4) {                                         \
            INS(ak0, ak1, ak2, ak3, ak4, ai0, ai1, ai2, ai3, ai4, a0, (JB));  \
            INS(ak0, ak1, ak2, ak3, ak4, ai0, ai1, ai2, ai3, ai4, a1, (JB) + 1); \
            INS(ck0, ck1, ck2, ck3, ck4, ci0, ci1, ci2, ci3, ci4, b0, (JB));  \
            INS(ck0, ck1, ck2, ck3, ck4, ci0, ci1, ci2, ci3, ci4, b1, (JB) + 1); \
        }                                                                     \
    }

    for (int m = 0; m < MPAIR; m += 4) {
        // Batched loads: 8 x LDS.128 back-to-back before any branch.
        ulonglong2 a0 = shA[m + 0], b0 = shB[m + 0];
        ulonglong2 a1 = shA[m + 1], b1 = shB[m + 1];
        ulonglong2 a2 = shA[m + 2], b2 = shB[m + 2];
        ulonglong2 a3 = shA[m + 3], b3 = shB[m + 3];
        const int jb = p0 + 2 * m;
        PAIR(a0, b0, jb + 0);
        PAIR(a1, b1, jb + 2);
        PAIR(a2, b2, jb + 4);
        PAIR(a3, b3, jb + 6);
    }
#undef PAIR
#undef INS

    const size_t oA = ((size_t)b * NPTS + qiA) * KNN;
    g_key[seg][oA + 0] = ak0;  g_idx[seg][oA + 0] = ai0;
    g_key[seg][oA + 1] = ak1;  g_idx[seg][oA + 1] = ai1;
    g_key[seg][oA + 2] = ak2;  g_idx[seg][oA + 2] = ai2;
    g_key[seg][oA + 3] = ak3;  g_idx[seg][oA + 3] = ai3;
    g_key[seg][oA + 4] = ak4;  g_idx[seg][oA + 4] = ai4;
    const size_t oB = ((size_t)b * NPTS + qiB) * KNN;
    g_key[seg][oB + 0] = ck0;  g_idx[seg][oB + 0] = ci0;
    g_key[seg][oB + 1] = ck1;  g_idx[seg][oB + 1] = ci1;
    g_key[seg][oB + 2] = ck2;  g_idx[seg][oB + 2] = ci2;
    g_key[seg][oB + 3] = ck3;  g_idx[seg][oB + 3] = ci3;
    g_key[seg][oB + 4] = ck4;  g_idx[seg][oB + 4] = ci4;
}

// --------------------------------------------------------------------------
// Kernel B: merge the four sorted 5-lists per query by rank counting.
// Global order = (key, segment, in-list position): earlier segment wins ties
// ('<=' vs '<'). Gather neighbors, compute covariance trace with the
// reference's centroid-then-centered numerics. Emits per-CTA partial sums.
// --------------------------------------------------------------------------
__global__ __launch_bounds__(256) void merge_trace_kernel(
    const float* __restrict__ pcd, float* __restrict__ out)
{
    __shared__ float warp_sums[8];

    const int t = blockIdx.x * 256 + threadIdx.x;   // 0 .. NB*NPTS-1
    const int b = t >> 12;

    float k[NSPLIT][KNN];
    int   ix[NSPLIT][KNN];
    const size_t o = (size_t)t * KNN;
#pragma unroll
    for (int s = 0; s < NSPLIT; s++)
#pragma unroll
        for (int i = 0; i < KNN; i++) {
            k[s][i]  = g_key[s][o + i];
            ix[s][i] = g_idx[s][o + i];
        }

    float w[NSPLIT][KNN];
#pragma unroll
    for (int s = 0; s < NSPLIT; s++) {
#pragma unroll
        for (int i = 0; i < KNN; i++) {
            int r = i;
#pragma unroll
            for (int u = 0; u < NSPLIT; u++) {
                if (u == s) continue;
#pragma unroll
                for (int j = 0; j < KNN; j++) {
                    if (u < s) r += (k[u][j] <= k[s][i]);
                    else       r += (k[u][j] <  k[s][i]);
                }
            }
            w[s][i] = (r < KNN) ? 1.0f : 0.0f;
        }
    }

    const float* base = pcd + (size_t)b * NPTS * 3;
    float px[NSPLIT][KNN], py[NSPLIT][KNN], pz[NSPLIT][KNN];
#pragma unroll
    for (int s = 0; s < NSPLIT; s++)
#pragma unroll
        for (int i = 0; i < KNN; i++) {
            int idx = ix[s][i];
            px[s][i] = base[idx * 3 + 0];
            py[s][i] = base[idx * 3 + 1];
            pz[s][i] = base[idx * 3 + 2];
        }

    float sx = 0.f, sy = 0.f, sz = 0.f;
#pragma unroll
    for (int s = 0; s < NSPLIT; s++)
#pragma unroll
        for (int i = 0; i < KNN; i++) {
            sx = fmaf(w[s][i], px[s][i], sx);
            sy = fmaf(w[s][i], py[s][i], sy);
            sz = fmaf(w[s][i], pz[s][i], sz);
        }
    const float inv_k = 1.0f / (float)KNN;
    const float mx = sx * inv_k, my = sy * inv_k, mz = sz * inv_k;

    float tr = 0.f;
#pragma unroll
    for (int s = 0; s < NSPLIT; s++)
#pragma unroll
        for (int i = 0; i < KNN; i++) {
            float dx = px[s][i] - mx, dy = py[s][i] - my, dz = pz[s][i] - mz;
            tr = fmaf(w[s][i], fmaf(dx, dx, fmaf(dy, dy, dz * dz)), tr);
        }
    tr *= 1.0f / (float)(KNN - 1);
    out[t] = tr;

    float s0 = tr;
#pragma unroll
    for (int off = 16; off > 0; off >>= 1)
        s0 += __shfl_down_sync(0xffffffffu, s0, off);
    if ((threadIdx.x & 31) == 0) warp_sums[threadIdx.x >> 5] = s0;
    __syncthreads();
    if (threadIdx.x < 32) {
        float v = (threadIdx.x < 8) ? warp_sums[threadIdx.x] : 0.0f;
#pragma unroll
        for (int off = 4; off > 0; off >>= 1)
            v += __shfl_down_sync(0xffffffffu, v, off);
        if (threadIdx.x == 0) g_partial[blockIdx.x] = v;
    }
}

// --------------------------------------------------------------------------
// Kernel C: normalize. 4 CTAs per batch; each redundantly sums its batch's
// 16 partials with a fixed-order tree (deterministic) and scales its quarter.
// --------------------------------------------------------------------------
__global__ __launch_bounds__(256) void finalize_kernel(float* __restrict__ out)
{
    __shared__ float s_inv;
    const int b = blockIdx.x >> 2;
    const int quarter = blockIdx.x & 3;

    if (threadIdx.x < 32) {
        float v = (threadIdx.x < 16) ? g_partial[b * 16 + threadIdx.x] : 0.0f;
#pragma unroll
        for (int off = 8; off > 0; off >>= 1)
            v += __shfl_down_sync(0xffffffffu, v, off);
        if (threadIdx.x == 0) s_inv = 1.0f / (v + 1e-8f);
    }
    __syncthreads();

    const float inv = s_inv;
    float* o = out + (size_t)b * NPTS + quarter * (NPTS / 4);
#pragma unroll
    for (int i = 0; i < (NPTS / 4) / 256; i++)
        o[i * 256 + threadIdx.x] *= inv;
}

extern "C" void kernel_launch(void* const* d_in, const int* in_sizes, int n_in,
                              void* d_out, int out_size)
{
    const float* pcd = (const float*)d_in[0];
    float* out = (float*)d_out;

    knn_scan_kernel<<<NB * CHUNKS * NSPLIT, TPB>>>(pcd);      // 512 CTAs
    merge_trace_kernel<<<(NB * NPTS) / 256, 256>>>(pcd, out); // 128 CTAs
    finalize_kernel<<<NB * 4, 256>>>(out);                    // 32 CTAs
}